// round 17
// baseline (speedup 1.0000x reference)
#include <cuda_runtime.h>

#define T_STEPS 32768
#define NSTEP   (T_STEPS - 1)    // 32767 RK4 steps; outputs x_1..x_32767
#define BATCH   32
#define NS      18
#define NH      16
#define FULL    0xffffffffu
typedef unsigned long long ull;

// ---------------- device scratch (static, no allocation) ----------------
__device__ float g_Phi[NS * NS];      // Phi fp32 (prologue direct steps)
__device__ float g_G[NH * NS];        // W1[:, :18]/STD (prologue)
__device__ float g_SP[24 * NS];       // state basis: Phi^d P*, d=0..7
__device__ float g_CP[21 * NH];       // policy basis: G Phi^{d-1} P*, d=1..7
__device__ float g_Wc[NS], g_Cc[NH];  // .5*sum_{1..8} Phi^d M / G Phi^{d-1} M
__device__ float g_hA[8][NS];         // .5*Phi^d M, d=1..8  ([d-1])
__device__ float g_hB[8][NH];         // .5*G Phi^{d-1} M, d=1..8
__device__ float g_hM[NS];            // .5*M
__device__ float g_cb[NH], g_wtow[NH], g_wtod[NH];
__device__ float g_w2m[NH];           // w2 * SCL
__device__ float g_sclv, g_cbr;
__device__ ull   g_PK[32 * NS];       // packed rows: lo=Phi8[lane], hi=GPhi7[lane&15]
__device__ ull   g_rec2[(NSTEP + 16) * 32];

// ---------------- packed f32x2 / activation helpers ----------------------
#define FMA2(acc, a, b)  asm("fma.rn.f32x2 %0, %1, %2, %0;" : "+l"(acc) : "l"(a), "l"(b))
#define PACKDUP(d, s)    asm("mov.b64 %0, {%1, %1};" : "=l"(d) : "f"(s))
#define PACK2(d, lo, hi) asm("mov.b64 %0, {%1, %2};" : "=l"(d) : "f"(lo), "f"(hi))
#define UNPACK2(lo, hi, v) asm("mov.b64 {%0, %1}, %2;" : "=f"(lo), "=f"(hi) : "l"(v))
#define ADD2(d, a, b)    asm("add.rn.f32x2 %0, %1, %2;" : "=l"(d) : "l"(a), "l"(b))
#define TANHA(d, s)      asm("tanh.approx.f32 %0, %1;" : "=f"(d) : "f"(s))
#define BARRIER()        asm volatile("bar.sync 0;" ::: "memory")

#define MAGICF 12582912.0f
#define KADJ   (0u - 31u * 0x4B400000u)
#define POLICYM(th_out, s_in) do {                                            \
    float h_; TANHA(h_, (s_in));                                              \
    float fb_ = fmaf(h_, w2m, MAGICF);                                        \
    unsigned su_ = __reduce_add_sync(FULL, __float_as_uint(fb_));             \
    float af_ = __uint_as_float(su_ + KADJ);                                  \
    float a_ = fmaf(af_, sclv, cbr);                                          \
    TANHA((th_out), a_);                                                      \
} while (0)

// ---------------- kernel 0: constants, fp64, 576 threads -----------------
__global__ void __launch_bounds__(576)
k_setup(const float* __restrict__ W_A, const float* __restrict__ W_B,
        const float* __restrict__ W1, const float* __restrict__ b1,
        const float* __restrict__ w2, const float* __restrict__ b2)
{
    __shared__ double A[324], T1[324], T2[324];
    __shared__ double PH[8][324];    // Phi^{d+1}
    __shared__ double GM[8][288];    // G Phi^d
    __shared__ double vt[NS], vr[NS], Md[NS], Pd[3][NS];
    __shared__ double s_scl;
    int t = threadIdx.x;
    int i = t / NS, j = t % NS;

    if (t < 324) A[t] = 1e-4 * (double)W_A[t] - (i == j ? 1e-3 : 0.0);
    if (t < NS) {
        vt[t] = 1e-6 * (double)W_B[t * 17 + 0];
        double s = 0.0;
        for (int c = 1; c < 17; c++) s += (double)W_B[t * 17 + c];
        vr[t] = s * (-16914.0 * 1e-6);
    }
    if (t < 288) GM[0][t] = (double)W1[(t / NS) * 20 + (t % NS)] / 1.41;
    if (t == 0) {
        double ss = 0.0;
        for (int k = 0; k < NH; k++) ss += fabs((double)w2[k]);
        double SCL = exp2(floor(20.0 - log2(ss > 1.0 ? ss : 1.0)));
        s_scl  = SCL;
        g_sclv = (float)(1.0 / (4.0 * SCL));
        g_cbr  = (float)(0.5 * (double)b2[0] - 12582912.0 / (4.0 * SCL));
    }
    __syncthreads();
    if (t < 324) { double s = 0; for (int k = 0; k < NS; k++) s += A[i*NS+k]*A[k*NS+j]; T1[t] = s; }
    __syncthreads();
    if (t < 324) { double s = 0; for (int k = 0; k < NS; k++) s += T1[i*NS+k]*A[k*NS+j]; T2[t] = s; }
    __syncthreads();
    if (t < 324) {
        double a4 = 0; for (int k = 0; k < NS; k++) a4 += T2[i*NS+k]*A[k*NS+j];
        PH[0][t] = (i == j ? 1.0 : 0.0) + 30.0*A[t] + 450.0*T1[t] + 4500.0*T2[t] + 33750.0*a4;
        g_Phi[t] = (float)PH[0][t];
    }
    if (t < NS) {
        double r1=0,r2=0,r3=0,u1=0,u2=0,u3=0;
        for (int k=0;k<NS;k++){ r1+=A[t*NS+k]*vr[k];  u1+=A[t*NS+k]*vt[k]; }
        for (int k=0;k<NS;k++){ r2+=T1[t*NS+k]*vr[k]; u2+=T1[t*NS+k]*vt[k]; }
        for (int k=0;k<NS;k++){ r3+=T2[t*NS+k]*vr[k]; u3+=T2[t*NS+k]*vt[k]; }
        Md[t]    = 30.0*vr[t] + 450.0*r1 + 4500.0*r2 + 33750.0*r3;
        Pd[0][t] =  5.0*vt[t] + 150.0*u1 + 2250.0*u2 + 33750.0*u3;
        Pd[1][t] = 20.0*vt[t] + 300.0*u1 + 2250.0*u2;
        Pd[2][t] =  5.0*vt[t];
        g_hM[t]  = (float)(0.5 * Md[t]);
    }
    __syncthreads();
    for (int d = 1; d < 8; d++) {                  // power chains to Phi^8 / GPhi^7
        if (t < 324) { double s=0; for (int k=0;k<NS;k++) s += PH[d-1][i*NS+k]*PH[0][k*NS+j]; PH[d][t]=s; }
        if (t < 288) { int m=t/NS, jj=t%NS; double s=0; for (int k=0;k<NS;k++) s += GM[d-1][m*NS+k]*PH[0][k*NS+jj]; GM[d][t]=s; }
        __syncthreads();
    }
    if (t < NS) {
        double wc = 0;
        for (int d = 1; d <= 8; d++) {
            double s = 0; for (int k = 0; k < NS; k++) s += PH[d-1][t*NS+k]*Md[k];
            g_hA[d-1][t] = (float)(0.5*s); wc += 0.5*s;
        }
        g_Wc[t] = (float)wc;
        for (int c = 0; c < 3; c++) g_SP[c*NS + t] = (float)Pd[c][t];
        for (int d = 1; d < 8; d++)
            for (int c = 0; c < 3; c++) {
                double s = 0; for (int k = 0; k < NS; k++) s += PH[d-1][t*NS+k]*Pd[c][k];
                g_SP[(3*d+c)*NS + t] = (float)s;
            }
    }
    if (t < NH) {
        double cc = 0;
        for (int d = 1; d <= 8; d++) {
            double s = 0; for (int k = 0; k < NS; k++) s += GM[d-1][t*NS+k]*Md[k];
            g_hB[d-1][t] = (float)(0.5*s); cc += 0.5*s;
        }
        g_Cc[t] = (float)cc;
        for (int d = 1; d <= 7; d++)
            for (int c = 0; c < 3; c++) {
                double s = 0; for (int k = 0; k < NS; k++) s += GM[d-1][t*NS+k]*Pd[c][k];
                g_CP[(3*(d-1)+c)*NH + t] = (float)s;
            }
        double srow = 0; for (int k = 0; k < NS; k++) srow += GM[0][t*NS+k];
        g_cb[t]   = (float)((double)b1[t] - 23.359 * srow);
        g_wtow[t] = W1[t * 20 + 18];
        g_wtod[t] = W1[t * 20 + 19];
        g_w2m[t]  = (float)((double)w2[t] * s_scl);
    }
    if (t < 288) g_G[t] = (float)GM[0][t];
    __syncthreads();
    if (t < 576) {
        int lane = t / NS, jj = t % NS;
        float lo = (lane < NS) ? (float)PH[7][lane*NS+jj] : 0.0f;   // Phi^8
        float hf = (float)GM[7][(lane & 15)*NS+jj];                 // G Phi^7
        g_PK[lane*NS + jj] = ((ull)__float_as_uint(hf) << 32) | (ull)__float_as_uint(lo);
    }
}

// ---------------- kernel 1: per-step packed records (depth-8) ------------
__global__ void k_steps(const float* __restrict__ t_eval, const float* __restrict__ Tt)
{
    int step = blockIdx.x * (blockDim.x >> 5) + (threadIdx.x >> 5);
    int lane = threadIdx.x & 31;
    if (step >= NSTEP) return;

    float t1[8], tm[8], tn[8];
#pragma unroll
    for (int d = 0; d < 8; d++) {
        int kk = step - d; if (kk < 0) kk = 0;
        t1[d] = Tt[kk]; tn[d] = Tt[kk + 1]; tm[d] = 0.5f * (t1[d] + tn[d]);
    }
    float t   = t_eval[step];
    float tod = fmodf(t, 86400.f) * (1.f / 86400.f);
    float tow = fmodf(t + 259200.f, 604800.f) * (1.f / 604800.f);

    float Wl = 0.f;
    if (lane < NS) {
        Wl = g_Wc[lane];
#pragma unroll
        for (int d = 0; d < 8; d++)
            Wl += t1[d] * g_SP[(3*d+0)*NS + lane] + tm[d] * g_SP[(3*d+1)*NS + lane]
                + tn[d] * g_SP[(3*d+2)*NS + lane];
    }
    int hi = lane & 15;
    float Cl = g_cb[hi] + g_wtow[hi] * tow + g_wtod[hi] * tod + g_Cc[hi];
#pragma unroll
    for (int d = 1; d <= 7; d++)
        Cl += t1[d] * g_CP[(3*(d-1)+0)*NH + hi] + tm[d] * g_CP[(3*(d-1)+1)*NH + hi]
            + tn[d] * g_CP[(3*(d-1)+2)*NH + hi];

    g_rec2[step * 32 + lane] = ((ull)__float_as_uint(Cl) << 32) | (ull)__float_as_uint(Wl);
}

// ---------------- kernel 2: warp-specialized scan, 3 warps ----------------
// A (warp0): th chain only, 1 bar per 4-step quad.
// B1 (warp1): AC matvec of quad z-entries 0,1;  B2 (warp2): entries 2,3.
// Pipeline lag 8: z (quad q) -> AC (quad q+1) -> consumed (quad q+2).
#define STEP_A(THa, PA, PB, PC, PD_, PE, PF, PG, Snew, Pnew, ACreg, Q, QOFF, ZSL, ZEN) do { \
    ull ZS_; ADD2(ZS_, ACreg, Q);                                             \
    FMA2(ZS_, PA, HB2); FMA2(ZS_, PB, HB3); FMA2(ZS_, PC, HB4);               \
    FMA2(ZS_, PD_, HB5); FMA2(ZS_, PE, HB6); FMA2(ZS_, PF, HB7);              \
    FMA2(ZS_, PG, HB8);                                                       \
    float zf_, sp_; UNPACK2(zf_, sp_, ZS_);                                   \
    float s_ = fmaf(THa, hB1, sp_);                                           \
    float h_; TANHA(h_, s_);                                                  \
    float fb_ = fmaf(h_, w2m, MAGICF);                                        \
    unsigned su_ = __reduce_add_sync(FULL, __float_as_uint(fb_));             \
    float af_ = __uint_as_float(su_ + KADJ);                                  \
    float a_ = fmaf(af_, sclv, cbr);                                          \
    TANHA(Snew, a_);                                                          \
    PACKDUP(Pnew, THa);                                                       \
    float z_ = fmaf(THa, hA1, zf_);                                           \
    if (sl) zbuf[ZSL][ZEN][lane] = make_float2(z_, z_);                       \
    float x_ = fmaf(Snew, hM, z_ + hM);                                       \
    if (sl) op[lane] = x_;                                                    \
    op += BATCH * NS;                                                         \
    Q = rqbase[QOFF];                                                         \
} while (0)

#define B_MAT(ZP, EOUT) do {                                                  \
    ull a0_ = 0ull, a1_ = 0ull, a2_ = 0ull, a3_ = 0ull;                       \
    const ulonglong2* zq_ = (const ulonglong2*)(ZP);                          \
    _Pragma("unroll")                                                         \
    for (int p_ = 0; p_ < 9; p_++) {                                          \
        ulonglong2 q_ = zq_[p_];                                              \
        if (p_ & 1) { FMA2(a2_, PK[2*p_], q_.x); FMA2(a3_, PK[2*p_+1], q_.y); }\
        else        { FMA2(a0_, PK[2*p_], q_.x); FMA2(a1_, PK[2*p_+1], q_.y); }\
    }                                                                         \
    ull u0_, u1_; ADD2(u0_, a0_, a2_); ADD2(u1_, a1_, a3_); ADD2(EOUT, u0_, u1_); \
} while (0)

__global__ void __launch_bounds__(96, 1)
k_scan(const float* __restrict__ iv, const float* __restrict__ t_eval,
       const float* __restrict__ Tt, float* __restrict__ out)
{
    __shared__ __align__(16) float2 zbuf[2][4][20];
    __shared__ __align__(16) ulonglong2 acbuf[2][2][32];
    int b = blockIdx.x, tid = threadIdx.x;
    int wid = tid >> 5, lane = tid & 31, hi = lane & 15;
    bool sl = (lane < NS);

    if (wid >= 1) {
        // ============ warps B1/B2: AC matvec engines ============
        ull PK[NS];
#pragma unroll
        for (int j = 0; j < NS; j++) PK[j] = g_PK[lane * NS + j];
        int bi = wid - 1;                 // 0: entries 0,1   1: entries 2,3
        BARRIER();                                    // pre-loop
        for (int g = 0; g < 4094; g++) {
            { ull e0, e1;                             // quad even: z from slot 1
              B_MAT(&zbuf[1][2*bi][0], e0);
              B_MAT(&zbuf[1][2*bi+1][0], e1);
              acbuf[1][bi][lane] = make_ulonglong2(e0, e1); }
            BARRIER();
            { ull e0, e1;                             // quad odd: z from slot 0
              B_MAT(&zbuf[0][2*bi][0], e0);
              B_MAT(&zbuf[0][2*bi+1][0], e1);
              acbuf[0][bi][lane] = make_ulonglong2(e0, e1); }
            BARRIER();
        }
        return;
    }

    // ================= warp A: sequential chain =================
    float hA1 = sl ? g_hA[0][lane] : 0.f;
    float hB1 = g_hB[0][hi];
    float hM  = sl ? g_hM[lane] : 0.f;
    float w2m = g_w2m[hi], sclv = g_sclv, cbr = g_cbr;
    ull HB2, HB3, HB4, HB5, HB6, HB7, HB8;           // packed (.5 Phi^d M, .5 G Phi^{d-1} M), d=2..8
    {
        float a, bb;
        a = sl ? g_hA[1][lane] : 0.f; bb = g_hB[1][hi]; PACK2(HB2, a, bb);
        a = sl ? g_hA[2][lane] : 0.f; bb = g_hB[2][hi]; PACK2(HB3, a, bb);
        a = sl ? g_hA[3][lane] : 0.f; bb = g_hB[3][hi]; PACK2(HB4, a, bb);
        a = sl ? g_hA[4][lane] : 0.f; bb = g_hB[4][hi]; PACK2(HB5, a, bb);
        a = sl ? g_hA[5][lane] : 0.f; bb = g_hB[5][hi]; PACK2(HB6, a, bb);
        a = sl ? g_hA[6][lane] : 0.f; bb = g_hB[6][hi]; PACK2(HB7, a, bb);
        a = sl ? g_hA[7][lane] : 0.f; bb = g_hB[7][hi]; PACK2(HB8, a, bb);
    }
    float Ph[NS], Gr[NS];
#pragma unroll
    for (int j = 0; j < NS; j++) {
        Ph[j] = sl ? g_Phi[lane * NS + j] : 0.f;
        Gr[j] = g_G[hi * NS + j];
    }
    float P1l = sl ? g_SP[0 * NS + lane] : 0.f;
    float Pml = sl ? g_SP[1 * NS + lane] : 0.f;
    float Pnl = sl ? g_SP[2 * NS + lane] : 0.f;
    float cbl = g_cb[hi], wtowl = g_wtow[hi], wtodl = g_wtod[hi];

    float x = sl ? iv[b * NS + lane] : 0.f;
    if (sl) out[b * NS + lane] = x;                  // row 0 = iv

    // ---- direct steps 0..14 (shuffle matvec) ----
    float zar[15], tha[15];
#pragma unroll
    for (int k = 0; k < 15; k++) {
        float ta = Tt[k], tb = Tt[k + 1], tmv = 0.5f * (ta + tb);
        float w = ta * P1l + tmv * Pml + tb * Pnl;
        float tv = t_eval[k];
        float tod = fmodf(tv, 86400.f) * (1.f / 86400.f);
        float tow = fmodf(tv + 259200.f, 604800.f) * (1.f / 604800.f);
        float s = cbl + wtowl * tow + wtodl * tod, z = w;
#pragma unroll
        for (int q = 0; q < NS; q++) {
            float xq = __shfl_sync(FULL, x, q);
            s = fmaf(Gr[q], xq, s);
            z = fmaf(Ph[q], xq, z);
        }
        float th; POLICYM(th, s);
        x = fmaf(th, hM, z + hM);
        if (sl) out[(k + 1) * BATCH * NS + b * NS + lane] = x;
        zar[k] = z; tha[k] = th;
    }

    // ---- seeds: acbuf[0] = AC(z7..z10); zbuf[1] = z11..z14 ----
    {
        ull ACz[4];
#pragma unroll
        for (int i2 = 0; i2 < 4; i2++) {
            ull acc = 0ull;
#pragma unroll
            for (int j = 0; j < NS; j++) {
                ull pk = g_PK[lane * NS + j];
                float zj = __shfl_sync(FULL, zar[7 + i2], j);
                ull zz; PACKDUP(zz, zj);
                FMA2(acc, pk, zz);
            }
            ACz[i2] = acc;
        }
        acbuf[0][0][lane] = make_ulonglong2(ACz[0], ACz[1]);
        acbuf[0][1][lane] = make_ulonglong2(ACz[2], ACz[3]);
        if (sl) {
            zbuf[1][0][lane] = make_float2(zar[11], zar[11]);
            zbuf[1][1][lane] = make_float2(zar[12], zar[12]);
            zbuf[1][2][lane] = make_float2(zar[13], zar[13]);
            zbuf[1][3][lane] = make_float2(zar[14], zar[14]);
        }
    }

    // th rings: S[i] = th_{7+i} (scalar), P[i] = packed th_{6+i}
    float S0 = tha[7], S1 = tha[8], S2 = tha[9],  S3 = tha[10];
    float S4 = tha[11], S5 = tha[12], S6 = tha[13], S7 = tha[14];
    ull P0, P1, P2, P3, P4, P5, P6, P7;
    PACKDUP(P0, tha[6]);  PACKDUP(P1, tha[7]);  PACKDUP(P2, tha[8]);
    PACKDUP(P3, tha[9]);  PACKDUP(P4, tha[10]); PACKDUP(P5, tha[11]);
    PACKDUP(P6, tha[12]); PACKDUP(P7, tha[13]);

    ull Q0 = g_rec2[15*32 + lane], Q1 = g_rec2[16*32 + lane];
    ull Q2 = g_rec2[17*32 + lane], Q3 = g_rec2[18*32 + lane];
    ull Q4 = g_rec2[19*32 + lane], Q5 = g_rec2[20*32 + lane];
    ull Q6 = g_rec2[21*32 + lane], Q7 = g_rec2[22*32 + lane];
    const ull* rqbase = g_rec2 + 23 * 32 + lane;
    float* op = out + 16 * BATCH * NS + b * NS;      // rows 16..32767

    BARRIER();                                       // pre-loop

    // ---- steady loop: steps 15..32766 = 32752 = 8 * 4094 ----
    for (int g = 0; g < 4094; g++) {
        ulonglong2 ACa = acbuf[0][0][lane];
        ulonglong2 ACb = acbuf[0][1][lane];
        STEP_A(S7, P7, P6, P5, P4, P3, P2, P1, S0, P0, ACa.x, Q0, 0*32, 0, 0);
        STEP_A(S0, P0, P7, P6, P5, P4, P3, P2, S1, P1, ACa.y, Q1, 1*32, 0, 1);
        STEP_A(S1, P1, P0, P7, P6, P5, P4, P3, S2, P2, ACb.x, Q2, 2*32, 0, 2);
        STEP_A(S2, P2, P1, P0, P7, P6, P5, P4, S3, P3, ACb.y, Q3, 3*32, 0, 3);
        BARRIER();
        ACa = acbuf[1][0][lane];
        ACb = acbuf[1][1][lane];
        STEP_A(S3, P3, P2, P1, P0, P7, P6, P5, S4, P4, ACa.x, Q4, 4*32, 1, 0);
        STEP_A(S4, P4, P3, P2, P1, P0, P7, P6, S5, P5, ACa.y, Q5, 5*32, 1, 1);
        STEP_A(S5, P5, P4, P3, P2, P1, P0, P7, S6, P6, ACb.x, Q6, 6*32, 1, 2);
        STEP_A(S6, P6, P5, P4, P3, P2, P1, P0, S7, P7, ACb.y, Q7, 7*32, 1, 3);
        BARRIER();
        rqbase += 8 * 32;
    }
}

// ---------------- launch ------------------------------------------------
extern "C" void kernel_launch(void* const* d_in, const int* in_sizes, int n_in,
                              void* d_out, int out_size)
{
    const float* t_eval = (const float*)d_in[0];
    const float* iv     = (const float*)d_in[1];
    const float* W_A    = (const float*)d_in[2];
    const float* W_B    = (const float*)d_in[3];
    const float* W1     = (const float*)d_in[4];
    const float* b1     = (const float*)d_in[5];
    const float* w2     = (const float*)d_in[6];
    const float* b2     = (const float*)d_in[7];
    const float* Tt     = (const float*)d_in[8];
    float* out = (float*)d_out;

    k_setup<<<1, 576>>>(W_A, W_B, W1, b1, w2, b2);
    k_steps<<<(NSTEP + 7) / 8, 256>>>(t_eval, Tt);
    k_scan<<<BATCH, 96>>>(iv, t_eval, Tt, out);
}